// round 14
// baseline (speedup 1.0000x reference)
#include <cuda_runtime.h>
#include <cuda_bf16.h>
#include <cstdint>
#include <cstddef>

#define BATCH   4096
#define TSTEPS  256
#define FDIM    64
#define G4      64      // 4*H
#define HID     16
#define DDIM    64
#define CH      8                    // timesteps per chunk
#define NCH     (TSTEPS / CH)        // 32 chunks

// ---------------- helpers ----------------
__device__ __forceinline__ uint32_t cvt2hi(float a, float b) {
    uint32_t r;
    asm("cvt.rn.bf16x2.f32 %0, %1, %2;" : "=r"(r) : "f"(b), "f"(a));
    return r;
}
__device__ __forceinline__ uint32_t cvt2lo(float a, float b, uint32_t h) {
    float ah = __uint_as_float(h << 16);
    float bh = __uint_as_float(h & 0xffff0000u);
    return cvt2hi(a - ah, b - bh);
}
__device__ __forceinline__ float sigm(float x) {
    float t;
    asm("tanh.approx.f32 %0, %1;" : "=f"(t) : "f"(0.5f * x));
    return fmaf(0.5f, t, 0.5f);
}
// warp-level bf16 MMA, sm_80+ (works on base sm_103 target)
__device__ __forceinline__ void mma16816(float* c, const uint32_t* a,
                                         uint32_t b0, uint32_t b1) {
    asm volatile(
        "mma.sync.aligned.m16n8k16.row.col.f32.bf16.bf16.f32 "
        "{%0,%1,%2,%3}, {%4,%5,%6,%7}, {%8,%9}, {%0,%1,%2,%3};"
        : "+f"(c[0]), "+f"(c[1]), "+f"(c[2]), "+f"(c[3])
        : "r"(a[0]), "r"(a[1]), "r"(a[2]), "r"(a[3]), "r"(b0), "r"(b1));
}

// ================= Fused kernel: GEMM chunk -> smem -> recurrence, per warp =================
// CTA = 128 threads = 4 warps. Warp w owns batch rows rA = blk*8+2w, rB = rA+1.
// Per chunk (8 timesteps): m16n64k64 GEMM (m rows 0-7 = rowA t0..t0+7, 8-15 = rowB),
// bf16 hi/lo split vs gate-permuted W in smem; stage gate tile (+bias) in per-warp smem;
// PREFETCH next chunk's x (LDG latency hidden behind recurrence); then 8 recurrence
// steps (lanes 0-15 = rowA, 16-31 = rowB). U staged in smem, reloaded per chunk so
// its registers are not live across the MMA phase.
__global__ void __launch_bounds__(128, 5)
fused_lstm_kernel(const float* __restrict__ xg, const float* __restrict__ Wg,
                  const float* __restrict__ Ug, const float* __restrict__ bg,
                  const float* __restrict__ Wdg, const float* __restrict__ bdg,
                  float* __restrict__ outg)
{
    // Bs[kp*68 + j] = (hi,lo) bf16x2 of {Bp[2kp][j], Bp[2kp+1][j]},
    // Bp[k][j] = W[k][(j%4)*16 + j/4]   (gate-permuted columns)
    __shared__ uint2 Bs[32 * 68];                       // 17408 B
    __shared__ __align__(16) float xw_s[4][2][CH][68];  // 17408 B, stride 68 (16B-mult)
    __shared__ __align__(16) float Us[HID][68];         // 4352 B, permuted U
    __shared__ float biasp_s[64];                       // permuted bias

    const int tid  = threadIdx.x;
    const int lane = tid & 31;
    const int w    = tid >> 5;
    const int g    = lane >> 2;    // MMA groupID 0..7
    const int kq   = lane & 3;     // MMA thread-in-group 0..3
    const int k    = lane & 15;    // hidden unit owned in recurrence
    const int half = lane >> 4;    // 0 = rowA, 1 = rowB

    // ---- build permuted B + U + bias in smem (once per CTA) ----
    for (int i = tid; i < 2048; i += 128) {
        int kp = i >> 6;                   // 0..31 (k = 2*kp)
        int j  = i & 63;                   // permuted output column
        int c  = (j & 3) * 16 + (j >> 2);  // original W column
        float w0 = Wg[(2 * kp)     * G4 + c];
        float w1 = Wg[(2 * kp + 1) * G4 + c];
        uint32_t hp = cvt2hi(w0, w1);
        Bs[kp * 68 + j] = make_uint2(hp, cvt2lo(w0, w1, hp));
    }
    for (int i = tid; i < HID * 64; i += 128) {
        int j   = i >> 6;                  // U row (hidden unit j)
        int col = i & 63;                  // permuted col = 4k + gate
        Us[j][col] = Ug[j * G4 + (col & 3) * 16 + (col >> 2)];
    }
    if (tid < 64) biasp_s[tid] = bg[(tid & 3) * 16 + (tid >> 2)];
    __syncthreads();

    const int rA = blockIdx.x * 8 + 2 * w;
    const float* xA = xg + (size_t)rA * TSTEPS * FDIM + 2 * kq;
    const float* xB = xA + TSTEPS * FDIM;

    float* wbufA = &xw_s[w][0][0][0];
    const float* mybuf = &xw_s[w][half][0][0] + 4 * k;

    float h = 0.0f, cc = 0.0f;

    // ---- preload chunk 0's A data ----
    float2 va[4][2], vb[4][2];
    {
        const float* pA = xA + (size_t)g * FDIM;
        const float* pB = xB + (size_t)g * FDIM;
        #pragma unroll
        for (int kk = 0; kk < 4; kk++) {
            #pragma unroll
            for (int hf = 0; hf < 2; hf++) {
                va[kk][hf] = *(const float2*)(pA + 16 * kk + 8 * hf);
                vb[kk][hf] = *(const float2*)(pB + 16 * kk + 8 * hf);
            }
        }
    }

    for (int ch = 0; ch < NCH; ch++) {
        float acc[8][4];
        #pragma unroll
        for (int n = 0; n < 8; n++)
            #pragma unroll
            for (int r = 0; r < 4; r++) acc[n][r] = 0.0f;

        // ---- per-kk: convert fragments (short live range), then MMAs ----
        #pragma unroll
        for (int kk = 0; kk < 4; kk++) {
            uint32_t fh[4], fl[4];
            fh[0] = cvt2hi(va[kk][0].x, va[kk][0].y);
            fh[1] = cvt2hi(vb[kk][0].x, vb[kk][0].y);
            fh[2] = cvt2hi(va[kk][1].x, va[kk][1].y);
            fh[3] = cvt2hi(vb[kk][1].x, vb[kk][1].y);
            fl[0] = cvt2lo(va[kk][0].x, va[kk][0].y, fh[0]);
            fl[1] = cvt2lo(vb[kk][0].x, vb[kk][0].y, fh[1]);
            fl[2] = cvt2lo(va[kk][1].x, va[kk][1].y, fh[2]);
            fl[3] = cvt2lo(vb[kk][1].x, vb[kk][1].y, fh[3]);

            #pragma unroll
            for (int n = 0; n < 8; n++) {
                int j = 8 * n + g;
                uint2 b0 = Bs[(kq + 8 * kk)     * 68 + j];
                uint2 b1 = Bs[(kq + 4 + 8 * kk) * 68 + j];
                mma16816(acc[n], fh, b0.x, b1.x);   // hi*hi
                mma16816(acc[n], fl, b0.x, b1.x);   // lo*hi
                mma16816(acc[n], fh, b0.y, b1.y);   // hi*lo
            }
        }

        // ---- stage gate tile (+bias) in smem ----
        __syncwarp();
        {
            float* rowAb = wbufA + g * 68;          // xw_s[w][0][g][*]
            float* rowBb = rowAb + CH * 68;         // xw_s[w][1][g][*]
            #pragma unroll
            for (int n = 0; n < 8; n++) {
                int j0 = 8 * n + 2 * kq;
                float2 bi = *(const float2*)&biasp_s[j0];
                *(float2*)(rowAb + j0) = make_float2(acc[n][0] + bi.x, acc[n][1] + bi.y);
                *(float2*)(rowBb + j0) = make_float2(acc[n][2] + bi.x, acc[n][3] + bi.y);
            }
        }
        __syncwarp();

        // ---- prefetch next chunk's A data (latency hidden behind recurrence) ----
        if (ch + 1 < NCH) {
            const float* pA = xA + (size_t)((ch + 1) * CH + g) * FDIM;
            const float* pB = xB + (size_t)((ch + 1) * CH + g) * FDIM;
            #pragma unroll
            for (int kk = 0; kk < 4; kk++) {
                #pragma unroll
                for (int hf = 0; hf < 2; hf++) {
                    va[kk][hf] = *(const float2*)(pA + 16 * kk + 8 * hf);
                    vb[kk][hf] = *(const float2*)(pB + 16 * kk + 8 * hf);
                }
            }
        }

        // ---- reload U into registers (live range = this chunk's recurrence only) ----
        float u0[HID], u1[HID], u2[HID], u3[HID];
        #pragma unroll
        for (int j = 0; j < HID; j++) {
            float4 uu = *(const float4*)&Us[j][4 * k];
            u0[j] = uu.x; u1[j] = uu.y; u2[j] = uu.z; u3[j] = uu.w;
        }

        // ---- recurrence: CH steps; lanes 0-15 rowA, 16-31 rowB ----
        #pragma unroll
        for (int tt = 0; tt < CH; tt++) {
            float4 cur = *(const float4*)(mybuf + tt * 68);

            float hj[HID];
            #pragma unroll
            for (int j = 0; j < HID; j++) hj[j] = __shfl_sync(0xffffffffu, h, j, 16);

            float z0a = cur.x, z1a = cur.y, z2a = cur.z, z3a = cur.w;
            float z0b = 0.f, z1b = 0.f, z2b = 0.f, z3b = 0.f;
            #pragma unroll
            for (int j = 0; j < 8; j++) {
                z0a = fmaf(hj[j], u0[j], z0a);
                z1a = fmaf(hj[j], u1[j], z1a);
                z2a = fmaf(hj[j], u2[j], z2a);
                z3a = fmaf(hj[j], u3[j], z3a);
                z0b = fmaf(hj[j + 8], u0[j + 8], z0b);
                z1b = fmaf(hj[j + 8], u1[j + 8], z1b);
                z2b = fmaf(hj[j + 8], u2[j + 8], z2b);
                z3b = fmaf(hj[j + 8], u3[j + 8], z3b);
            }
            float ig = sigm(z0a + z0b);
            float fg = sigm(z1a + z1b);
            float gg = fmaxf(z2a + z2b, 0.0f);
            float og = sigm(z3a + z3b);
            cc = fmaf(fg, cc, ig * gg);
            h  = og * fmaxf(cc, 0.0f);
        }
    }

    // ---- dense: out = sigmoid(h @ Wd + bd); thread k -> cols 4k..4k+3 ----
    float hj[HID];
    #pragma unroll
    for (int j = 0; j < HID; j++) hj[j] = __shfl_sync(0xffffffffu, h, j, 16);

    float a0 = 0.f, a1 = 0.f, a2 = 0.f, a3 = 0.f;
    #pragma unroll
    for (int j = 0; j < HID; j++) {
        float4 w4 = *(const float4*)(Wdg + j * DDIM + 4 * k);
        a0 = fmaf(hj[j], w4.x, a0);
        a1 = fmaf(hj[j], w4.y, a1);
        a2 = fmaf(hj[j], w4.z, a2);
        a3 = fmaf(hj[j], w4.w, a3);
    }
    float4 bd4 = *(const float4*)(bdg + 4 * k);
    a0 = sigm(a0 + bd4.x);
    a1 = sigm(a1 + bd4.y);
    a2 = sigm(a2 + bd4.z);
    a3 = sigm(a3 + bd4.w);

    float s = a0 + a1 + a2 + a3;
    #pragma unroll
    for (int off = 8; off; off >>= 1) s += __shfl_xor_sync(0xffffffffu, s, off, 16);
    float inv = __fdividef(1.0f, s);

    float4 o4 = make_float4(a0 * inv, a1 * inv, a2 * inv, a3 * inv);
    *((float4*)(outg + (size_t)(rA + half) * DDIM + 4 * k)) = o4;
}

// ================= launch =================
extern "C" void kernel_launch(void* const* d_in, const int* in_sizes, int n_in,
                              void* d_out, int out_size)
{
    const float* x  = (const float*)d_in[0];
    const float* W  = (const float*)d_in[1];
    const float* U  = (const float*)d_in[2];
    const float* b  = (const float*)d_in[3];
    const float* Wd = (const float*)d_in[4];
    const float* bd = (const float*)d_in[5];
    float* out = (float*)d_out;

    // raise the smem carveout so 5 CTAs x 39.4KB fit per SM
    cudaFuncSetAttribute(fused_lstm_kernel,
                         cudaFuncAttributePreferredSharedMemoryCarveout, 100);

    fused_lstm_kernel<<<BATCH / 8, 128>>>(x, W, U, b, Wd, bd, out);
}

// round 15
// speedup vs baseline: 1.3053x; 1.3053x over previous
#include <cuda_runtime.h>
#include <cuda_bf16.h>
#include <cstdint>
#include <cstddef>

#define BATCH   4096
#define TSTEPS  256
#define FDIM    64
#define G4      64      // 4*H
#define HID     16
#define DDIM    64
#define CH      8                    // timesteps per chunk
#define NCH     (TSTEPS / CH)        // 32 chunks

// ---------------- helpers ----------------
__device__ __forceinline__ uint32_t cvt2hi(float a, float b) {
    uint32_t r;
    asm("cvt.rn.bf16x2.f32 %0, %1, %2;" : "=r"(r) : "f"(b), "f"(a));
    return r;
}
__device__ __forceinline__ uint32_t cvt2lo(float a, float b, uint32_t h) {
    float ah = __uint_as_float(h << 16);
    float bh = __uint_as_float(h & 0xffff0000u);
    return cvt2hi(a - ah, b - bh);
}
__device__ __forceinline__ float sigm(float x) {
    float t;
    asm("tanh.approx.f32 %0, %1;" : "=f"(t) : "f"(0.5f * x));
    return fmaf(0.5f, t, 0.5f);
}
// packed f32x2 ops (sm_100-family PTX; full fp32 precision)
__device__ __forceinline__ uint64_t packf2(float lo, float hi) {
    uint64_t r;
    asm("mov.b64 %0, {%1, %2};" : "=l"(r) : "f"(lo), "f"(hi));
    return r;
}
__device__ __forceinline__ uint64_t fmaf2(uint64_t a, uint64_t b, uint64_t c) {
    uint64_t d;
    asm("fma.rn.f32x2 %0, %1, %2, %3;" : "=l"(d) : "l"(a), "l"(b), "l"(c));
    return d;
}
__device__ __forceinline__ float hsumf2(uint64_t v) {
    float lo, hi;
    asm("mov.b64 {%0, %1}, %2;" : "=f"(lo), "=f"(hi) : "l"(v));
    return lo + hi;
}
// warp-level bf16 MMA, sm_80+ (works on base sm_103 target)
__device__ __forceinline__ void mma16816(float* c, const uint32_t* a,
                                         uint32_t b0, uint32_t b1) {
    asm volatile(
        "mma.sync.aligned.m16n8k16.row.col.f32.bf16.bf16.f32 "
        "{%0,%1,%2,%3}, {%4,%5,%6,%7}, {%8,%9}, {%0,%1,%2,%3};"
        : "+f"(c[0]), "+f"(c[1]), "+f"(c[2]), "+f"(c[3])
        : "r"(a[0]), "r"(a[1]), "r"(a[2]), "r"(a[3]), "r"(b0), "r"(b1));
}

// ================= Fused kernel: GEMM chunk -> smem -> recurrence, per warp =================
// CTA = 128 threads = 4 warps. Warp w owns batch rows rA = blk*8+2w, rB = rA+1.
// Per chunk (8 timesteps): m16n64k64 GEMM (m rows 0-7 = rowA t0..t0+7, 8-15 = rowB),
// bf16 hi/lo split vs gate-permuted W in smem; stage gate tile (+bias) in per-warp smem;
// then 8 recurrence steps (lanes 0-15 = rowA, 16-31 = rowB) with packed f32x2 FMA:
// each gate's accumulator = (even-j, odd-j) partial sums in one f32x2.
__global__ void __launch_bounds__(128, 4)
fused_lstm_kernel(const float* __restrict__ xg, const float* __restrict__ Wg,
                  const float* __restrict__ Ug, const float* __restrict__ bg,
                  const float* __restrict__ Wdg, const float* __restrict__ bdg,
                  float* __restrict__ outg)
{
    // Bs[kp*68 + j] = (hi,lo) bf16x2 of {Bp[2kp][j], Bp[2kp+1][j]},
    // Bp[k][j] = W[k][(j%4)*16 + j/4]   (gate-permuted columns)
    __shared__ uint2 Bs[32 * 68];                       // 17408 B
    __shared__ __align__(16) float xw_s[4][2][CH][68];  // 17408 B, stride 68 (16B-mult)
    __shared__ float biasp_s[64];                       // permuted bias

    const int tid  = threadIdx.x;
    const int lane = tid & 31;
    const int w    = tid >> 5;
    const int g    = lane >> 2;    // MMA groupID 0..7
    const int kq   = lane & 3;     // MMA thread-in-group 0..3
    const int k    = lane & 15;    // hidden unit owned in recurrence
    const int half = lane >> 4;    // 0 = rowA, 1 = rowB

    // ---- build permuted B + bias in smem (once per CTA) ----
    for (int i = tid; i < 2048; i += 128) {
        int kp = i >> 6;                   // 0..31 (k = 2*kp)
        int j  = i & 63;                   // permuted output column
        int c  = (j & 3) * 16 + (j >> 2);  // original W column
        float w0 = Wg[(2 * kp)     * G4 + c];
        float w1 = Wg[(2 * kp + 1) * G4 + c];
        uint32_t hp = cvt2hi(w0, w1);
        Bs[kp * 68 + j] = make_uint2(hp, cvt2lo(w0, w1, hp));
    }
    if (tid < 64) biasp_s[tid] = bg[(tid & 3) * 16 + (tid >> 2)];
    __syncthreads();

    // ---- recurrence constants: U pre-packed into (even-j, odd-j) f32x2 pairs ----
    uint64_t u0p[8], u1p[8], u2p[8], u3p[8];
    #pragma unroll
    for (int jj = 0; jj < 8; jj++) {
        const float* ue = Ug + (2 * jj)     * G4;
        const float* uo = Ug + (2 * jj + 1) * G4;
        u0p[jj] = packf2(ue[k],      uo[k]);
        u1p[jj] = packf2(ue[k + 16], uo[k + 16]);
        u2p[jj] = packf2(ue[k + 32], uo[k + 32]);
        u3p[jj] = packf2(ue[k + 48], uo[k + 48]);
    }

    const int rA = blockIdx.x * 8 + 2 * w;
    const float* xA = xg + (size_t)rA * TSTEPS * FDIM + 2 * kq;
    const float* xB = xA + TSTEPS * FDIM;

    float* wbufA = &xw_s[w][0][0][0];
    const float* mybuf = &xw_s[w][half][0][0] + 4 * k;

    float h = 0.0f, cc = 0.0f;

    for (int ch = 0; ch < NCH; ch++) {
        const int t0 = ch * CH;

        // ---- A loads: rowA & rowB, t = t0+g, all 64 k (16 x LDG.64, batched) ----
        float2 va[4][2], vb[4][2];
        {
            const float* pA = xA + (size_t)(t0 + g) * FDIM;
            const float* pB = xB + (size_t)(t0 + g) * FDIM;
            #pragma unroll
            for (int kk = 0; kk < 4; kk++) {
                #pragma unroll
                for (int hf = 0; hf < 2; hf++) {
                    va[kk][hf] = *(const float2*)(pA + 16 * kk + 8 * hf);
                    vb[kk][hf] = *(const float2*)(pB + 16 * kk + 8 * hf);
                }
            }
        }

        float acc[8][4];
        #pragma unroll
        for (int n = 0; n < 8; n++)
            #pragma unroll
            for (int r = 0; r < 4; r++) acc[n][r] = 0.0f;

        // ---- per-kk: convert fragments (short live range), then MMAs ----
        #pragma unroll
        for (int kk = 0; kk < 4; kk++) {
            uint32_t fh[4], fl[4];
            fh[0] = cvt2hi(va[kk][0].x, va[kk][0].y);
            fh[1] = cvt2hi(vb[kk][0].x, vb[kk][0].y);
            fh[2] = cvt2hi(va[kk][1].x, va[kk][1].y);
            fh[3] = cvt2hi(vb[kk][1].x, vb[kk][1].y);
            fl[0] = cvt2lo(va[kk][0].x, va[kk][0].y, fh[0]);
            fl[1] = cvt2lo(vb[kk][0].x, vb[kk][0].y, fh[1]);
            fl[2] = cvt2lo(va[kk][1].x, va[kk][1].y, fh[2]);
            fl[3] = cvt2lo(vb[kk][1].x, vb[kk][1].y, fh[3]);

            #pragma unroll
            for (int n = 0; n < 8; n++) {
                int j = 8 * n + g;
                uint2 b0 = Bs[(kq + 8 * kk)     * 68 + j];
                uint2 b1 = Bs[(kq + 4 + 8 * kk) * 68 + j];
                mma16816(acc[n], fh, b0.x, b1.x);   // hi*hi
                mma16816(acc[n], fl, b0.x, b1.x);   // lo*hi
                mma16816(acc[n], fh, b0.y, b1.y);   // hi*lo
            }
        }

        // ---- stage gate tile (+bias) in smem ----
        __syncwarp();
        {
            float* rowAb = wbufA + g * 68;          // xw_s[w][0][g][*]
            float* rowBb = rowAb + CH * 68;         // xw_s[w][1][g][*]
            #pragma unroll
            for (int n = 0; n < 8; n++) {
                int j0 = 8 * n + 2 * kq;
                float2 bi = *(const float2*)&biasp_s[j0];
                *(float2*)(rowAb + j0) = make_float2(acc[n][0] + bi.x, acc[n][1] + bi.y);
                *(float2*)(rowBb + j0) = make_float2(acc[n][2] + bi.x, acc[n][3] + bi.y);
            }
        }
        __syncwarp();

        // ---- recurrence: CH steps; lanes 0-15 rowA, 16-31 rowB ----
        #pragma unroll
        for (int tt = 0; tt < CH; tt++) {
            float4 cur = *(const float4*)(mybuf + tt * 68);

            // gate accumulators: (even-j sum, odd-j sum) packed
            uint64_t z0 = packf2(cur.x, 0.0f);
            uint64_t z1 = packf2(cur.y, 0.0f);
            uint64_t z2 = packf2(cur.z, 0.0f);
            uint64_t z3 = packf2(cur.w, 0.0f);

            #pragma unroll
            for (int jj = 0; jj < 8; jj++) {
                float he = __shfl_sync(0xffffffffu, h, 2 * jj,     16);
                float ho = __shfl_sync(0xffffffffu, h, 2 * jj + 1, 16);
                uint64_t hp = packf2(he, ho);
                z0 = fmaf2(hp, u0p[jj], z0);
                z1 = fmaf2(hp, u1p[jj], z1);
                z2 = fmaf2(hp, u2p[jj], z2);
                z3 = fmaf2(hp, u3p[jj], z3);
            }

            float ig = sigm(hsumf2(z0));
            float fg = sigm(hsumf2(z1));
            float gg = fmaxf(hsumf2(z2), 0.0f);
            float og = sigm(hsumf2(z3));
            cc = fmaf(fg, cc, ig * gg);
            h  = og * fmaxf(cc, 0.0f);
        }
    }

    // ---- dense: out = sigmoid(h @ Wd + bd); thread k -> cols 4k..4k+3 ----
    float hj[HID];
    #pragma unroll
    for (int j = 0; j < HID; j++) hj[j] = __shfl_sync(0xffffffffu, h, j, 16);

    float a0 = 0.f, a1 = 0.f, a2 = 0.f, a3 = 0.f;
    #pragma unroll
    for (int j = 0; j < HID; j++) {
        float4 w4 = *(const float4*)(Wdg + j * DDIM + 4 * k);
        a0 = fmaf(hj[j], w4.x, a0);
        a1 = fmaf(hj[j], w4.y, a1);
        a2 = fmaf(hj[j], w4.z, a2);
        a3 = fmaf(hj[j], w4.w, a3);
    }
    float4 bd4 = *(const float4*)(bdg + 4 * k);
    a0 = sigm(a0 + bd4.x);
    a1 = sigm(a1 + bd4.y);
    a2 = sigm(a2 + bd4.z);
    a3 = sigm(a3 + bd4.w);

    float s = a0 + a1 + a2 + a3;
    #pragma unroll
    for (int off = 8; off; off >>= 1) s += __shfl_xor_sync(0xffffffffu, s, off, 16);
    float inv = __fdividef(1.0f, s);

    float4 o4 = make_float4(a0 * inv, a1 * inv, a2 * inv, a3 * inv);
    *((float4*)(outg + (size_t)(rA + half) * DDIM + 4 * k)) = o4;
}

// ================= launch =================
extern "C" void kernel_launch(void* const* d_in, const int* in_sizes, int n_in,
                              void* d_out, int out_size)
{
    const float* x  = (const float*)d_in[0];
    const float* W  = (const float*)d_in[1];
    const float* U  = (const float*)d_in[2];
    const float* b  = (const float*)d_in[3];
    const float* Wd = (const float*)d_in[4];
    const float* bd = (const float*)d_in[5];
    float* out = (float*)d_out;

    fused_lstm_kernel<<<BATCH / 8, 128>>>(x, W, U, b, Wd, bd, out);
}